// round 1
// baseline (speedup 1.0000x reference)
#include <cuda_runtime.h>
#include <math_constants.h>

// Problem shape (fixed by the dataset)
#define BATCH   16
#define CDIM    256
#define HWDIM   1024          // 32*32
#define N_TOK   16384         // BATCH * HWDIM
#define K_CODES 8192

#define ZQ_ELEMS (BATCH * CDIM * HWDIM)   // 4194304
#define IX_ELEMS N_TOK                     // 16384

// Scratch (device globals — no allocation allowed)
__device__ float g_znorm[N_TOK];
__device__ float g_enorm[K_CODES];
__device__ int   g_idx[N_TOK];

// ---------------------------------------------------------------------------
// Kernel 1: row norms  znorm[n] = sum_c z[n,c]^2,  enorm[k] = sum_c e[k,c]^2
// ---------------------------------------------------------------------------
__global__ void norms_kernel(const float* __restrict__ z,
                             const float* __restrict__ emb) {
    int t = blockIdx.x * blockDim.x + threadIdx.x;
    if (t < N_TOK) {
        int b = t >> 10, hw = t & 1023;
        const float* p = z + (size_t)b * (CDIM * HWDIM) + hw;
        float s = 0.f;
        #pragma unroll 8
        for (int c = 0; c < CDIM; ++c) {
            float v = p[(size_t)c * HWDIM];
            s = __fmaf_rn(v, v, s);
        }
        g_znorm[t] = s;
    } else if (t < N_TOK + K_CODES) {
        int k = t - N_TOK;
        const float* p = emb + (size_t)k * CDIM;
        float s = 0.f;
        #pragma unroll 8
        for (int c = 0; c < CDIM; ++c) {
            float v = p[c];
            s = __fmaf_rn(v, v, s);
        }
        g_enorm[k] = s;
    }
}

// ---------------------------------------------------------------------------
// Kernel 2: argmin over codes.
// Block = 128 tokens, 256 threads (16x16), 8x8 register micro-tile.
// z tile [256 c][128 m] resident in smem; embedding streamed in 128-code
// chunks, 8 c-columns at a time, double buffered.
// ---------------------------------------------------------------------------
__global__ void __launch_bounds__(256, 1)
argmin_kernel(const float* __restrict__ z, const float* __restrict__ emb) {
    extern __shared__ float smem[];
    float (*As)[128] = (float (*)[128])smem;                       // [256][128]
    float (*Bs)[8][128] = (float (*)[8][128])(smem + CDIM * 128);  // [2][8][128]

    const int m0 = blockIdx.x * 128;
    const int b  = m0 >> 10;          // tile never straddles a batch image
    const int hw0 = m0 & 1023;
    const int tid = threadIdx.x;
    const int tx = tid & 15;
    const int ty = tid >> 4;

    // --- load z tile: As[c][m] = z[b, c, hw0+m] (coalesced float4) ---
    const float* zbase = z + (size_t)b * (CDIM * HWDIM) + hw0;
    #pragma unroll
    for (int i = 0; i < 32; ++i) {
        int v = tid + i * 256;            // 8192 float4 total
        int c = v >> 5, m4 = v & 31;
        float4 q4 = *(const float4*)(zbase + (size_t)c * HWDIM + m4 * 4);
        *(float4*)&As[c][m4 * 4] = q4;
    }

    float znr[8];
    #pragma unroll
    for (int i = 0; i < 8; ++i) znr[i] = g_znorm[m0 + ty * 8 + i];

    float best_d[8];
    int   best_i[8];
    #pragma unroll
    for (int i = 0; i < 8; ++i) { best_d[i] = CUDART_INF_F; best_i[i] = 0; }

    // --- prologue: stage iter 0 of embedding chunk ---
    const int kk = tid >> 1;          // code row within chunk (0..127)
    const int qq = tid & 1;           // which float4 of the 8-c slice
    float4 stage = *(const float4*)(emb + (size_t)kk * CDIM + qq * 4);
    Bs[0][qq * 4 + 0][kk] = stage.x;
    Bs[0][qq * 4 + 1][kk] = stage.y;
    Bs[0][qq * 4 + 2][kk] = stage.z;
    Bs[0][qq * 4 + 3][kk] = stage.w;
    __syncthreads();

    float acc[8][8];
    #pragma unroll
    for (int i = 0; i < 8; ++i)
        #pragma unroll
        for (int j = 0; j < 8; ++j) acc[i][j] = 0.f;

    int cur = 0;
    const int NITER = (K_CODES / 128) * (CDIM / 8);   // 64 * 32 = 2048

    for (int t = 0; t < NITER; ++t) {
        // prefetch next slice into registers (overlaps with compute)
        if (t + 1 < NITER) {
            int kc = (t + 1) >> 5;
            int c0 = ((t + 1) & 31) * 8;
            stage = *(const float4*)(emb + (size_t)(kc * 128 + kk) * CDIM + c0 + qq * 4);
        }

        const int cbase = (t & 31) * 8;
        #pragma unroll
        for (int cc = 0; cc < 8; ++cc) {
            float4 a0 = *(float4*)&As[cbase + cc][ty * 8];
            float4 a1 = *(float4*)&As[cbase + cc][ty * 8 + 4];
            float4 b0 = *(float4*)&Bs[cur][cc][tx * 8];
            float4 b1 = *(float4*)&Bs[cur][cc][tx * 8 + 4];
            float av[8] = {a0.x, a0.y, a0.z, a0.w, a1.x, a1.y, a1.z, a1.w};
            float bv[8] = {b0.x, b0.y, b0.z, b0.w, b1.x, b1.y, b1.z, b1.w};
            #pragma unroll
            for (int i = 0; i < 8; ++i)
                #pragma unroll
                for (int j = 0; j < 8; ++j)
                    acc[i][j] = __fmaf_rn(av[i], bv[j], acc[i][j]);
        }

        // end of a 128-code chunk: fold into running min (k ascending)
        if ((t & 31) == 31) {
            const int k0 = (t >> 5) * 128;
            float en[8];
            #pragma unroll
            for (int j = 0; j < 8; ++j) en[j] = g_enorm[k0 + tx * 8 + j];
            #pragma unroll
            for (int i = 0; i < 8; ++i) {
                #pragma unroll
                for (int j = 0; j < 8; ++j) {
                    // replicate reference rounding: fl(fl(zn+en) - fl(2*dot))
                    float s = __fadd_rn(znr[i], en[j]);
                    float d = __fsub_rn(s, __fmul_rn(2.0f, acc[i][j]));
                    if (d < best_d[i]) {          // strict <, k ascending => first-min
                        best_d[i] = d;
                        best_i[i] = k0 + tx * 8 + j;
                    }
                    acc[i][j] = 0.f;
                }
            }
        }

        // commit staged slice to the alternate buffer
        if (t + 1 < NITER) {
            Bs[cur ^ 1][qq * 4 + 0][kk] = stage.x;
            Bs[cur ^ 1][qq * 4 + 1][kk] = stage.y;
            Bs[cur ^ 1][qq * 4 + 2][kk] = stage.z;
            Bs[cur ^ 1][qq * 4 + 3][kk] = stage.w;
            __syncthreads();
            cur ^= 1;
        }
    }

    // --- cross-thread reduction over tx (16 partials per token) ---
    __syncthreads();
    float* red_d = smem;                 // [128][16]
    int*   red_i = (int*)(smem + 128 * 16);
    #pragma unroll
    for (int i = 0; i < 8; ++i) {
        red_d[(ty * 8 + i) * 16 + tx] = best_d[i];
        red_i[(ty * 8 + i) * 16 + tx] = best_i[i];
    }
    __syncthreads();
    if (tid < 128) {
        float bd = red_d[tid * 16];
        int   bi = red_i[tid * 16];
        #pragma unroll
        for (int x = 1; x < 16; ++x) {
            float d = red_d[tid * 16 + x];
            int   ii = red_i[tid * 16 + x];
            if (d < bd || (d == bd && ii < bi)) { bd = d; bi = ii; }
        }
        g_idx[m0 + tid] = bi;
    }
}

// ---------------------------------------------------------------------------
// Kernel 3: outputs.  One block per token, 256 threads = channel.
//  z_q (BCHW, straight-through fl(z + fl(e-z))), loss (BHWC, fl(0.25*d2+d2)),
//  idx as float. Offsets < 0 mean "don't write".
// ---------------------------------------------------------------------------
__global__ void output_kernel(const float* __restrict__ z,
                              const float* __restrict__ emb,
                              float* __restrict__ out,
                              int zq_off, int loss_off, int idx_off) {
    int n = blockIdx.x;
    int c = threadIdx.x;
    int b = n >> 10, hw = n & 1023;
    int idx = g_idx[n];

    float e  = emb[(size_t)idx * CDIM + c];
    float zv = z[(size_t)b * (CDIM * HWDIM) + (size_t)c * HWDIM + hw];

    float dq = __fsub_rn(e, zv);                 // z_q - z (stop-grad equal)
    float zq = __fadd_rn(zv, dq);                // straight-through estimator
    float d2 = __fmul_rn(dq, dq);
    float loss = __fadd_rn(__fmul_rn(0.25f, d2), d2);

    if (zq_off >= 0)
        out[(size_t)zq_off + (size_t)b * (CDIM * HWDIM) + (size_t)c * HWDIM + hw] = zq;
    if (loss_off >= 0)
        out[(size_t)loss_off + (size_t)n * CDIM + c] = loss;
    if (idx_off >= 0 && c == 0)
        out[(size_t)idx_off + n] = (float)idx;
}

// ---------------------------------------------------------------------------
extern "C" void kernel_launch(void* const* d_in, const int* in_sizes, int n_in,
                              void* d_out, int out_size) {
    // Defensive input identification by size: z has 4194304 elems, emb 2097152.
    const float* z   = (const float*)d_in[0];
    const float* emb = (const float*)d_in[1];
    if (n_in >= 2 && in_sizes[0] == K_CODES * CDIM && in_sizes[1] == ZQ_ELEMS) {
        z   = (const float*)d_in[1];
        emb = (const float*)d_in[0];
    }
    float* out = (float*)d_out;

    norms_kernel<<<(N_TOK + K_CODES + 255) / 256, 256>>>(z, emb);

    const int smem_bytes = (CDIM * 128 + 2 * 8 * 128) * (int)sizeof(float); // 139264
    cudaFuncSetAttribute(argmin_kernel,
                         cudaFuncAttributeMaxDynamicSharedMemorySize, smem_bytes);
    argmin_kernel<<<N_TOK / 128, 256, smem_bytes>>>(z, emb);

    // Decide output layout from out_size at runtime (metadata not visible here).
    int zq_off = -1, loss_off = -1, idx_off = -1;
    if (out_size == 2 * ZQ_ELEMS + IX_ELEMS) {        // [z_q | loss | idx]
        zq_off = 0; loss_off = ZQ_ELEMS; idx_off = 2 * ZQ_ELEMS;
    } else if (out_size == 2 * ZQ_ELEMS) {            // [z_q | loss]
        zq_off = 0; loss_off = ZQ_ELEMS;
    } else if (out_size == ZQ_ELEMS + IX_ELEMS) {     // [z_q | idx]
        zq_off = 0; idx_off = ZQ_ELEMS;
    } else if (out_size == ZQ_ELEMS) {                // [z_q]
        zq_off = 0;
    } else if (out_size == IX_ELEMS) {                // [idx]
        idx_off = 0;
    } else {                                           // best effort, fill in order
        int rem = out_size;
        if (rem >= ZQ_ELEMS) { zq_off = 0; rem -= ZQ_ELEMS; }
        if (rem >= ZQ_ELEMS) { loss_off = ZQ_ELEMS; rem -= ZQ_ELEMS; }
        if (rem >= IX_ELEMS) { idx_off = out_size - IX_ELEMS; }
    }

    output_kernel<<<N_TOK, 256>>>(z, emb, out, zq_off, loss_off, idx_off);
}